// round 14
// baseline (speedup 1.0000x reference)
#include <cuda_runtime.h>
#include <cstdint>

#define IN_F   4096
#define OUT_F  4096
#define B_DIM  4096

// 64 MB dense weight scratch (tf32-rounded at scatter time)
// + 64 MB tf32-rounded activation scratch.
__device__ float g_W[(size_t)OUT_F * IN_F];
__device__ float g_X[(size_t)B_DIM * IN_F];

__device__ __forceinline__ float rna_tf32(float v) {
    uint32_t r;
    asm("cvt.rna.tf32.f32 %0, %1;" : "=r"(r) : "f"(v));
    return __uint_as_float(r);
}

// ---------------------------------------------------------------------------
// Kernel 1: fused prep — zero W and round x -> g_X in one grid-stride pass.
// ---------------------------------------------------------------------------
__global__ void prep_kernel(const float* __restrict__ x) {
    size_t n4 = (size_t)OUT_F * IN_F / 4;
    float4* w4 = reinterpret_cast<float4*>(g_W);
    float4* xo = reinterpret_cast<float4*>(g_X);
    const float4* xi = reinterpret_cast<const float4*>(x);
    size_t stride = (size_t)gridDim.x * blockDim.x;
    for (size_t i = (size_t)blockIdx.x * blockDim.x + threadIdx.x; i < n4; i += stride) {
        w4[i] = make_float4(0.f, 0.f, 0.f, 0.f);
        float4 v = xi[i];
        v.x = rna_tf32(v.x); v.y = rna_tf32(v.y);
        v.z = rna_tf32(v.z); v.w = rna_tf32(v.w);
        xo[i] = v;
    }
}

// ---------------------------------------------------------------------------
// Kernel 2: COO scatter, value pre-rounded to tf32 (validated rel_err 3.1e-4)
// ---------------------------------------------------------------------------
__global__ void scatter_kernel(const float* __restrict__ vals,
                               const int* __restrict__ rows,
                               const int* __restrict__ cols, int nnz) {
    int i = blockIdx.x * blockDim.x + threadIdx.x;
    if (i < nnz)
        atomicAdd(&g_W[(size_t)rows[i] * IN_F + cols[i]], rna_tf32(vals[i]));
}

// ---------------------------------------------------------------------------
// Kernel 3: tf32 mma.sync GEMM  out = g_X @ g_W^T + bias
// CTA 128(M) x 64(N), 128 threads (4 warps as 2m x 2n, warp tile 64x32 —
// the proven R9 inner loop). Grid 2048 CTAs -> ~7 waves, tail idle 1.2%
// (vs 13.5% at 1024 CTAs, the measured residual loss).
// BK=32, 3-stage cp.async, ldmatrix.x4, double-buffered fragments.
// ---------------------------------------------------------------------------
#define BM 128
#define BN 64
#define BK 32
#define KITERS (IN_F / BK)              // 128
#define NSTAGE 3
#define SA 36                           // floats per SMEM row (pad 4)
#define A_TILE_B (BM * SA * 4)          // 18432
#define B_TILE_B (BN * SA * 4)          // 9216
#define STAGE_B  (A_TILE_B + B_TILE_B)  // 27648
#define SMEM_BYTES (NSTAGE * STAGE_B)   // 82944 -> 2 CTAs/SM

__device__ __forceinline__ void cp_async16(uint32_t saddr, const void* gptr) {
    asm volatile("cp.async.cg.shared.global [%0], [%1], 16;"
                 :: "r"(saddr), "l"(gptr) : "memory");
}

__device__ __forceinline__ uint32_t smem_u32(const void* p) {
    uint32_t a;
    asm("{ .reg .u64 t; cvta.to.shared.u64 t, %1; cvt.u32.u64 %0, t; }"
        : "=r"(a) : "l"(p));
    return a;
}

__device__ __forceinline__ void ldsm_x4(uint32_t& r0, uint32_t& r1,
                                        uint32_t& r2, uint32_t& r3,
                                        uint32_t addr) {
    asm volatile("ldmatrix.sync.aligned.m8n8.x4.shared.b16 {%0,%1,%2,%3}, [%4];"
                 : "=r"(r0), "=r"(r1), "=r"(r2), "=r"(r3) : "r"(addr));
}

// Non-volatile: pure register op; ptxas may interleave HMMA with later LDSM.
__device__ __forceinline__ void mma_tf32(float* c, const uint32_t* a,
                                         const uint32_t* b) {
    asm("mma.sync.aligned.m16n8k8.row.col.f32.tf32.tf32.f32 "
        "{%0,%1,%2,%3}, {%4,%5,%6,%7}, {%8,%9}, {%0,%1,%2,%3};"
        : "+f"(c[0]), "+f"(c[1]), "+f"(c[2]), "+f"(c[3])
        : "r"(a[0]), "r"(a[1]), "r"(a[2]), "r"(a[3]), "r"(b[0]), "r"(b[1]));
}

__global__ __launch_bounds__(128, 2)
void gemm_mma_kernel(const float* __restrict__ bias, float* __restrict__ out) {
    extern __shared__ float smem[];
    const uint32_t sb = smem_u32(smem);

    const int tid  = threadIdx.x;
    const int wid  = tid >> 5;
    const int lane = tid & 31;
    const int wm   = wid & 1;        // 0..1 -> 64 M-rows
    const int wn   = wid >> 1;       // 0..1 -> 32 N-cols
    const int g    = lane >> 2;
    const int tig  = lane & 3;

    const int m0 = blockIdx.y * BM;
    const int n0 = blockIdx.x * BN;

    const float* Ag = g_X + (size_t)m0 * IN_F;
    const float* Bg = g_W + (size_t)n0 * IN_F;

    // cp.async coords: 16B chunks, 8 per 128B(=BK) row; 128 threads.
    // A: 1024 chunks -> 8/thread (rows tid>>3 + j*16, j<8)
    // B: 512 chunks  -> 4/thread (rows tid>>3 + j*16, j<4)
    const int crow0 = tid >> 3;
    const int cc8   = tid & 7;

    const int a_row = (lane & 7) + ((lane >> 3) & 1) * 8;
    const int a_col = (lane >> 4) * 4;
    uint32_t a_base[4];
#pragma unroll
    for (int i = 0; i < 4; i++)
        a_base[i] = sb + (uint32_t)(((wm * 64 + i * 16 + a_row) * SA + a_col) * 4);
    const int b_row = ((lane >> 4) & 1) * 8 + (lane & 7);
    const int b_col = ((lane >> 3) & 1) * 4;
    uint32_t b_base[2];
#pragma unroll
    for (int p = 0; p < 2; p++)
        b_base[p] = sb + (uint32_t)A_TILE_B +
                    (uint32_t)(((wn * 32 + p * 16 + b_row) * SA + b_col) * 4);

    float acc[4][4][4];
#pragma unroll
    for (int i = 0; i < 4; i++)
#pragma unroll
        for (int j = 0; j < 4; j++)
#pragma unroll
            for (int r = 0; r < 4; r++) acc[i][j][r] = 0.f;

    // ---- prologue: prefetch stages 0,1 ----
#pragma unroll
    for (int st = 0; st < 2; st++) {
        const int k0 = st * BK;
        const uint32_t ab = sb + st * STAGE_B;
        const uint32_t bb = ab + A_TILE_B;
#pragma unroll
        for (int j = 0; j < 8; j++) {
            int row = crow0 + j * 16;
            uint32_t so = (uint32_t)(row * (SA * 4) + cc8 * 16);
            cp_async16(ab + so, Ag + (size_t)row * IN_F + k0 + cc8 * 4);
        }
#pragma unroll
        for (int j = 0; j < 4; j++) {
            int row = crow0 + j * 16;
            uint32_t so = (uint32_t)(row * (SA * 4) + cc8 * 16);
            cp_async16(bb + so, Bg + (size_t)row * IN_F + k0 + cc8 * 4);
        }
        asm volatile("cp.async.commit_group;" ::: "memory");
    }

    // ---- mainloop ----
    for (int ci = 0; ci < KITERS; ci++) {
        asm volatile("cp.async.wait_group 1;" ::: "memory");
        __syncthreads();

        const uint32_t soff = (uint32_t)((ci % NSTAGE) * STAGE_B);

        uint32_t af[2][4][4];
        uint32_t bf[2][4][2];

        // kk=0 fragment loads before the prefetch burst
#pragma unroll
        for (int i = 0; i < 4; i++)
            ldsm_x4(af[0][i][0], af[0][i][1], af[0][i][2], af[0][i][3],
                    a_base[i] + soff);
#pragma unroll
        for (int p = 0; p < 2; p++)
            ldsm_x4(bf[0][2 * p][0], bf[0][2 * p][1], bf[0][2 * p + 1][0],
                    bf[0][2 * p + 1][1], b_base[p] + soff);

        // prefetch stage ci+2
        if (ci + 2 < KITERS) {
            const int st = (ci + 2) % NSTAGE;
            const int k0 = (ci + 2) * BK;
            const uint32_t ab = sb + st * STAGE_B;
            const uint32_t bb = ab + A_TILE_B;
#pragma unroll
            for (int j = 0; j < 8; j++) {
                int row = crow0 + j * 16;
                uint32_t so = (uint32_t)(row * (SA * 4) + cc8 * 16);
                cp_async16(ab + so, Ag + (size_t)row * IN_F + k0 + cc8 * 4);
            }
#pragma unroll
            for (int j = 0; j < 4; j++) {
                int row = crow0 + j * 16;
                uint32_t so = (uint32_t)(row * (SA * 4) + cc8 * 16);
                cp_async16(bb + so, Bg + (size_t)row * IN_F + k0 + cc8 * 4);
            }
        }
        asm volatile("cp.async.commit_group;" ::: "memory");

        // pipelined kk loop: load kk+1 frags, then mma kk
#pragma unroll
        for (int kk = 0; kk < 4; kk++) {
            const int cur = kk & 1, nxt = cur ^ 1;
            if (kk < 3) {
                const uint32_t ko = soff + (kk + 1) * 32;
#pragma unroll
                for (int i = 0; i < 4; i++)
                    ldsm_x4(af[nxt][i][0], af[nxt][i][1], af[nxt][i][2],
                            af[nxt][i][3], a_base[i] + ko);
#pragma unroll
                for (int p = 0; p < 2; p++)
                    ldsm_x4(bf[nxt][2 * p][0], bf[nxt][2 * p][1],
                            bf[nxt][2 * p + 1][0], bf[nxt][2 * p + 1][1],
                            b_base[p] + ko);
            }
#pragma unroll
            for (int i = 0; i < 4; i++)
#pragma unroll
                for (int j = 0; j < 4; j++)
                    mma_tf32(acc[i][j], af[cur][i], bf[cur][j]);
        }
    }

    // ---- epilogue: bias + dense stores ----
#pragma unroll
    for (int i = 0; i < 4; i++) {
        const int row = m0 + wm * 64 + i * 16 + g;
#pragma unroll
        for (int j = 0; j < 4; j++) {
            const int col = n0 + wn * 32 + j * 8 + tig * 2;
            float2 bv = *reinterpret_cast<const float2*>(bias + col);
            float2 v0 = make_float2(acc[i][j][0] + bv.x, acc[i][j][1] + bv.y);
            float2 v1 = make_float2(acc[i][j][2] + bv.x, acc[i][j][3] + bv.y);
            *reinterpret_cast<float2*>(out + (size_t)row * OUT_F + col) = v0;
            *reinterpret_cast<float2*>(out + (size_t)(row + 8) * OUT_F + col) = v1;
        }
    }
}

// ---------------------------------------------------------------------------
// kernel_launch: prep(zeroW+roundX) -> scatter -> mma GEMM
// Inputs: x, values, rows, cols, bias
// ---------------------------------------------------------------------------
extern "C" void kernel_launch(void* const* d_in, const int* in_sizes, int n_in,
                              void* d_out, int out_size) {
    const float* x    = (const float*)d_in[0];
    const float* vals = (const float*)d_in[1];
    const int*   rows = (const int*)d_in[2];
    const int*   cols = (const int*)d_in[3];
    const float* bias = (const float*)d_in[4];
    float*       out  = (float*)d_out;
    const int nnz = in_sizes[1];

    cudaFuncSetAttribute(gemm_mma_kernel,
                         cudaFuncAttributeMaxDynamicSharedMemorySize, SMEM_BYTES);

    prep_kernel<<<2048, 256>>>(x);
    scatter_kernel<<<(nnz + 255) / 256, 256>>>(vals, rows, cols, nnz);
    dim3 grid(OUT_F / BN, B_DIM / BM);
    gemm_mma_kernel<<<grid, 128, SMEM_BYTES>>>(bias, out);
}

// round 15
// speedup vs baseline: 1.0858x; 1.0858x over previous
#include <cuda_runtime.h>
#include <cstdint>

#define IN_F   4096
#define OUT_F  4096
#define B_DIM  4096

// 64 MB dense weight scratch (tf32-rounded at scatter time).
__device__ float g_W[(size_t)OUT_F * IN_F];

__device__ __forceinline__ float rna_tf32(float v) {
    uint32_t r;
    asm("cvt.rna.tf32.f32 %0, %1;" : "=r"(r) : "f"(v));
    return __uint_as_float(r);
}

// ---------------------------------------------------------------------------
// Kernel 1: zero dense W (write-only; graph replays re-run the scatter)
// ---------------------------------------------------------------------------
__global__ void zero_w_kernel() {
    size_t n4 = (size_t)OUT_F * IN_F / 4;
    float4* p = reinterpret_cast<float4*>(g_W);
    size_t stride = (size_t)gridDim.x * blockDim.x;
    for (size_t i = (size_t)blockIdx.x * blockDim.x + threadIdx.x; i < n4; i += stride)
        p[i] = make_float4(0.f, 0.f, 0.f, 0.f);
}

// ---------------------------------------------------------------------------
// Kernel 2: COO scatter, value pre-rounded to tf32 (validated rel_err 3.1e-4)
// ---------------------------------------------------------------------------
__global__ void scatter_kernel(const float* __restrict__ vals,
                               const int* __restrict__ rows,
                               const int* __restrict__ cols, int nnz) {
    int i = blockIdx.x * blockDim.x + threadIdx.x;
    if (i < nnz)
        atomicAdd(&g_W[(size_t)rows[i] * IN_F + cols[i]], rna_tf32(vals[i]));
}

// ---------------------------------------------------------------------------
// Kernel 3: tf32 mma.sync GEMM  out = x @ g_W^T + bias   (R9 proven schedule)
// CTA 128x128, 8 warps (2m x 4n, warp tile 64x32), 2 CTAs/SM, BK=32,
// 3-stage cp.async, ldmatrix.x4, double-buffered fragments.
// NEW: A is loaded RAW from x; RNA-to-tf32 is applied in registers by adding
// 0x1000 (half-ulp at the tf32 truncation point) to each A fragment — the
// MMA's low-13-bit truncation then yields round-to-nearest. This deletes the
// 128MB g_X scratch pass entirely.
// ---------------------------------------------------------------------------
#define BM 128
#define BN 128
#define BK 32
#define KITERS (IN_F / BK)              // 128
#define NSTAGE 3
#define SA 36                           // floats per SMEM row (pad 4)
#define A_TILE_B (BM * SA * 4)          // 18432
#define STAGE_B  (2 * A_TILE_B)         // 36864
#define SMEM_BYTES (NSTAGE * STAGE_B)   // 110592 -> 2 CTAs/SM

__device__ __forceinline__ void cp_async16(uint32_t saddr, const void* gptr) {
    asm volatile("cp.async.cg.shared.global [%0], [%1], 16;"
                 :: "r"(saddr), "l"(gptr) : "memory");
}

__device__ __forceinline__ uint32_t smem_u32(const void* p) {
    uint32_t a;
    asm("{ .reg .u64 t; cvta.to.shared.u64 t, %1; cvt.u32.u64 %0, t; }"
        : "=r"(a) : "l"(p));
    return a;
}

__device__ __forceinline__ void ldsm_x4(uint32_t& r0, uint32_t& r1,
                                        uint32_t& r2, uint32_t& r3,
                                        uint32_t addr) {
    asm volatile("ldmatrix.sync.aligned.m8n8.x4.shared.b16 {%0,%1,%2,%3}, [%4];"
                 : "=r"(r0), "=r"(r1), "=r"(r2), "=r"(r3) : "r"(addr));
}

// Non-volatile: pure register op; ptxas may interleave HMMA with later LDSM.
__device__ __forceinline__ void mma_tf32(float* c, const uint32_t* a,
                                         const uint32_t* b) {
    asm("mma.sync.aligned.m16n8k8.row.col.f32.tf32.tf32.f32 "
        "{%0,%1,%2,%3}, {%4,%5,%6,%7}, {%8,%9}, {%0,%1,%2,%3};"
        : "+f"(c[0]), "+f"(c[1]), "+f"(c[2]), "+f"(c[3])
        : "r"(a[0]), "r"(a[1]), "r"(a[2]), "r"(a[3]), "r"(b[0]), "r"(b[1]));
}

// RNA half-ulp bump for tf32 truncation (fp32 bit pattern, sign-magnitude:
// +0x1000 rounds the magnitude half-away; carry into exponent is correct).
__device__ __forceinline__ void rna_bump4(uint32_t* r) {
    r[0] += 0x1000u; r[1] += 0x1000u; r[2] += 0x1000u; r[3] += 0x1000u;
}

__global__ __launch_bounds__(256, 2)
void gemm_mma_kernel(const float* __restrict__ x,
                     const float* __restrict__ bias, float* __restrict__ out) {
    extern __shared__ float smem[];
    const uint32_t sb = smem_u32(smem);

    const int tid  = threadIdx.x;
    const int wid  = tid >> 5;
    const int lane = tid & 31;
    const int wm   = wid & 1;
    const int wn   = wid >> 1;
    const int g    = lane >> 2;
    const int tig  = lane & 3;

    const int m0 = blockIdx.y * BM;
    const int n0 = blockIdx.x * BN;

    const float* Ag = x   + (size_t)m0 * IN_F;
    const float* Bg = g_W + (size_t)n0 * IN_F;

    const int crow0 = tid >> 3;
    const int cc8   = tid & 7;

    const int a_row = (lane & 7) + ((lane >> 3) & 1) * 8;
    const int a_col = (lane >> 4) * 4;
    uint32_t a_base[4];
#pragma unroll
    for (int i = 0; i < 4; i++)
        a_base[i] = sb + (uint32_t)(((wm * 64 + i * 16 + a_row) * SA + a_col) * 4);
    const int b_row = ((lane >> 4) & 1) * 8 + (lane & 7);
    const int b_col = ((lane >> 3) & 1) * 4;
    uint32_t b_base[2];
#pragma unroll
    for (int p = 0; p < 2; p++)
        b_base[p] = sb + (uint32_t)A_TILE_B +
                    (uint32_t)(((wn * 32 + p * 16 + b_row) * SA + b_col) * 4);

    float acc[4][4][4];
#pragma unroll
    for (int i = 0; i < 4; i++)
#pragma unroll
        for (int j = 0; j < 4; j++)
#pragma unroll
            for (int r = 0; r < 4; r++) acc[i][j][r] = 0.f;

    // ---- prologue: prefetch stages 0,1 ----
#pragma unroll
    for (int st = 0; st < 2; st++) {
        const int k0 = st * BK;
        const uint32_t ab = sb + st * STAGE_B;
        const uint32_t bb = ab + A_TILE_B;
#pragma unroll
        for (int j = 0; j < 4; j++) {
            int row = crow0 + j * 32;
            uint32_t so = (uint32_t)(row * (SA * 4) + cc8 * 16);
            cp_async16(ab + so, Ag + (size_t)row * IN_F + k0 + cc8 * 4);
            cp_async16(bb + so, Bg + (size_t)row * IN_F + k0 + cc8 * 4);
        }
        asm volatile("cp.async.commit_group;" ::: "memory");
    }

    // ---- mainloop ----
    for (int ci = 0; ci < KITERS; ci++) {
        asm volatile("cp.async.wait_group 1;" ::: "memory");
        __syncthreads();

        const uint32_t soff = (uint32_t)((ci % NSTAGE) * STAGE_B);

        uint32_t af[2][4][4];
        uint32_t bf[2][4][2];

        // kk=0 fragment loads before the prefetch burst
#pragma unroll
        for (int i = 0; i < 4; i++)
            ldsm_x4(af[0][i][0], af[0][i][1], af[0][i][2], af[0][i][3],
                    a_base[i] + soff);
#pragma unroll
        for (int p = 0; p < 2; p++)
            ldsm_x4(bf[0][2 * p][0], bf[0][2 * p][1], bf[0][2 * p + 1][0],
                    bf[0][2 * p + 1][1], b_base[p] + soff);
#pragma unroll
        for (int i = 0; i < 4; i++) rna_bump4(af[0][i]);

        // prefetch stage ci+2
        if (ci + 2 < KITERS) {
            const int st = (ci + 2) % NSTAGE;
            const int k0 = (ci + 2) * BK;
            const uint32_t ab = sb + st * STAGE_B;
            const uint32_t bb = ab + A_TILE_B;
#pragma unroll
            for (int j = 0; j < 4; j++) {
                int row = crow0 + j * 32;
                uint32_t so = (uint32_t)(row * (SA * 4) + cc8 * 16);
                cp_async16(ab + so, Ag + (size_t)row * IN_F + k0 + cc8 * 4);
                cp_async16(bb + so, Bg + (size_t)row * IN_F + k0 + cc8 * 4);
            }
        }
        asm volatile("cp.async.commit_group;" ::: "memory");

        // pipelined kk loop: load kk+1 frags, then mma kk
#pragma unroll
        for (int kk = 0; kk < 4; kk++) {
            const int cur = kk & 1, nxt = cur ^ 1;
            if (kk < 3) {
                const uint32_t ko = soff + (kk + 1) * 32;
#pragma unroll
                for (int i = 0; i < 4; i++)
                    ldsm_x4(af[nxt][i][0], af[nxt][i][1], af[nxt][i][2],
                            af[nxt][i][3], a_base[i] + ko);
#pragma unroll
                for (int p = 0; p < 2; p++)
                    ldsm_x4(bf[nxt][2 * p][0], bf[nxt][2 * p][1],
                            bf[nxt][2 * p + 1][0], bf[nxt][2 * p + 1][1],
                            b_base[p] + ko);
#pragma unroll
                for (int i = 0; i < 4; i++) rna_bump4(af[nxt][i]);
            }
#pragma unroll
            for (int i = 0; i < 4; i++)
#pragma unroll
                for (int j = 0; j < 4; j++)
                    mma_tf32(acc[i][j], af[cur][i], bf[cur][j]);
        }
    }

    // ---- epilogue: bias + dense stores ----
#pragma unroll
    for (int i = 0; i < 4; i++) {
        const int row = m0 + wm * 64 + i * 16 + g;
#pragma unroll
        for (int j = 0; j < 4; j++) {
            const int col = n0 + wn * 32 + j * 8 + tig * 2;
            float2 bv = *reinterpret_cast<const float2*>(bias + col);
            float2 v0 = make_float2(acc[i][j][0] + bv.x, acc[i][j][1] + bv.y);
            float2 v1 = make_float2(acc[i][j][2] + bv.x, acc[i][j][3] + bv.y);
            *reinterpret_cast<float2*>(out + (size_t)row * OUT_F + col) = v0;
            *reinterpret_cast<float2*>(out + (size_t)(row + 8) * OUT_F + col) = v1;
        }
    }
}

// ---------------------------------------------------------------------------
// kernel_launch: zeroW -> scatter(+roundW) -> mma GEMM (reads x directly)
// Inputs: x, values, rows, cols, bias
// ---------------------------------------------------------------------------
extern "C" void kernel_launch(void* const* d_in, const int* in_sizes, int n_in,
                              void* d_out, int out_size) {
    const float* x    = (const float*)d_in[0];
    const float* vals = (const float*)d_in[1];
    const int*   rows = (const int*)d_in[2];
    const int*   cols = (const int*)d_in[3];
    const float* bias = (const float*)d_in[4];
    float*       out  = (float*)d_out;
    const int nnz = in_sizes[1];

    cudaFuncSetAttribute(gemm_mma_kernel,
                         cudaFuncAttributeMaxDynamicSharedMemorySize, SMEM_BYTES);

    zero_w_kernel<<<2048, 256>>>();
    scatter_kernel<<<(nnz + 255) / 256, 256>>>(vals, rows, cols, nnz);
    dim3 grid(OUT_F / BN, B_DIM / BM);
    gemm_mma_kernel<<<grid, 256, SMEM_BYTES>>>(x, bias, out);
}